// round 8
// baseline (speedup 1.0000x reference)
#include <cuda_runtime.h>

#define ALPHA 0.2f
#define B_   8
#define G_   8
#define V_   1024
#define FOUT_ 64
#define C_   512
#define OUTW_ 60
#define OUTC_ 120

// ---------------- scratch ----------------
__device__ __align__(16) float    g_Wh[B_*V_*C_];
__device__ float                  g_Spart[B_*16*C_];
__device__ float                  g_S[B_*C_];
__device__ unsigned               g_rowmask[B_*V_*32];
__device__ int                    g_zcol[B_*V_];
__device__ __align__(16) float    g_featin[B_*G_*V_*FOUT_];
__device__ __align__(16) float    g_featout[B_*G_*V_*FOUT_];

__device__ __forceinline__ float lrelu(float x) { return x >= 0.f ? x : ALPHA * x; }

// Winograd F(2,5) filter transform G' (6x5), points {0,1,-1,2,-2,inf}
__device__ const float c_G[6][5] = {
    { 0.25f, 0.f, 0.f, 0.f, 0.f },
    {-1.f/6.f, -1.f/6.f, -1.f/6.f, -1.f/6.f, -1.f/6.f },
    {-1.f/6.f,  1.f/6.f, -1.f/6.f,  1.f/6.f, -1.f/6.f },
    { 1.f/24.f, 2.f/24.f, 4.f/24.f, 8.f/24.f, 16.f/24.f },
    { 1.f/24.f,-2.f/24.f, 4.f/24.f,-8.f/24.f, 16.f/24.f },
    { 0.f, 0.f, 0.f, 0.f, 1.f }
};

__global__ void k_zero() {
    int t = blockIdx.x * blockDim.x + threadIdx.x;
    if (t < B_ * V_) g_zcol[t] = 0;
}

__global__ void __launch_bounds__(256) k_adj(const int* __restrict__ adj) {
    int i = blockIdx.x, b = blockIdx.y;
    __shared__ unsigned mask[32];
    int t = threadIdx.x;
    if (t < 32) mask[t] = 0u;
    __syncthreads();
    const int4* p = (const int4*)(adj + (size_t)b * G_ * V_ * V_ + (size_t)i * V_);
    int4 acc = p[t];
#pragma unroll
    for (int g = 1; g < G_; g++) {
        int4 v = p[(size_t)g * (V_ * (V_ / 4)) + t];
        acc.x |= v.x; acc.y |= v.y; acc.z |= v.z; acc.w |= v.w;
    }
    unsigned nib = (unsigned)(acc.x == 0) | ((unsigned)(acc.y == 0) << 1) |
                   ((unsigned)(acc.z == 0) << 2) | ((unsigned)(acc.w == 0) << 3);
    if (nib) {
        atomicOr(&mask[t >> 3], nib << ((t & 7) * 4));
        int jb = b * V_ + 4 * t;
        if (acc.x == 0) atomicAdd(&g_zcol[jb + 0], 1);
        if (acc.y == 0) atomicAdd(&g_zcol[jb + 1], 1);
        if (acc.z == 0) atomicAdd(&g_zcol[jb + 2], 1);
        if (acc.w == 0) atomicAdd(&g_zcol[jb + 3], 1);
    }
    __syncthreads();
    if (t < 32) g_rowmask[((size_t)b * V_ + i) * 32 + t] = mask[t];
}

__global__ void __launch_bounds__(256) k_wh(const float* __restrict__ h,
                                            const float* __restrict__ W) {
    __shared__ __align__(16) float sW[64 * 64];
    __shared__ __align__(16) float sH[64 * 64];
    __shared__ float red[64 * 17];
    int t = threadIdx.x;
    int vt = blockIdx.x, g = blockIdx.y, b = blockIdx.z;
    const float4* wp = (const float4*)(W + (size_t)g * 4096);
    const float4* hp = (const float4*)(h + (((size_t)b * G_ + g) * V_ + (size_t)vt * 64) * 64);
    float4* sw4 = (float4*)sW;
    float4* sh4 = (float4*)sH;
#pragma unroll
    for (int q = t; q < 1024; q += 256) { sw4[q] = wp[q]; sh4[q] = hp[q]; }
    __syncthreads();
    int tx = t & 15, ty = t >> 4;
    int o0 = tx * 4, r0 = ty * 4;
    float acc[4][4] = {};
#pragma unroll 4
    for (int i = 0; i < 64; i++) {
        float4 bb = *(const float4*)(sW + i * 64 + o0);
#pragma unroll
        for (int r = 0; r < 4; r++) {
            float a = sH[(r0 + r) * 64 + i];
            acc[r][0] += a * bb.x; acc[r][1] += a * bb.y;
            acc[r][2] += a * bb.z; acc[r][3] += a * bb.w;
        }
    }
    float cs[4] = {0.f, 0.f, 0.f, 0.f};
#pragma unroll
    for (int r = 0; r < 4; r++) {
        float4 v;
        v.x = lrelu(acc[r][0]); v.y = lrelu(acc[r][1]);
        v.z = lrelu(acc[r][2]); v.w = lrelu(acc[r][3]);
        size_t row = (size_t)b * V_ + vt * 64 + r0 + r;
        *(float4*)(g_Wh + row * C_ + g * 64 + o0) = v;
        cs[0] += v.x; cs[1] += v.y; cs[2] += v.z; cs[3] += v.w;
    }
    __syncthreads();
#pragma unroll
    for (int j = 0; j < 4; j++) red[(o0 + j) * 17 + ty] = cs[j];
    __syncthreads();
    if (t < 64) {
        float s = 0.f;
#pragma unroll
        for (int k = 0; k < 16; k++) s += red[t * 17 + k];
        g_Spart[((size_t)b * 16 + vt) * C_ + g * 64 + t] = s;
    }
}

__global__ void k_sreduce() {
    int b = blockIdx.x >> 3;
    int c = (blockIdx.x & 7) * 64 + threadIdx.x;
    float s = 0.f;
#pragma unroll
    for (int vt = 0; vt < 16; vt++) s += g_Spart[((size_t)b * 16 + vt) * C_ + c];
    g_S[b * C_ + c] = s;
}

__global__ void __launch_bounds__(512) k_feat() {
    int i = blockIdx.x, b = blockIdx.y;
    int c = threadIdx.x;
    __shared__ short jlist[64];
    __shared__ int njs;
    __shared__ float sdeg;
    if (c == 0) sdeg = (float)(V_ - g_zcol[b * V_ + i]) * (1.0f / V_);
    if (c < 32) {
        unsigned mw = g_rowmask[((size_t)b * V_ + i) * 32 + c];
        int cnt = __popc(mw);
        int pre = cnt;
#pragma unroll
        for (int d = 1; d < 32; d <<= 1) {
            int v = __shfl_up_sync(0xffffffffu, pre, d);
            if (c >= d) pre += v;
        }
        int excl = pre - cnt;
        if (c == 31) njs = pre;
        while (mw) {
            int p = __ffs(mw) - 1;
            mw &= mw - 1;
            jlist[excl++] = (short)(c * 32 + p);
        }
    }
    __syncthreads();
    float S = g_S[b * C_ + c];
    float corr = 0.f;
    int n = njs;
    const float* whb = g_Wh + (size_t)b * V_ * C_ + c;
#pragma unroll 1
    for (int k = 0; k < n; k += 4) {
        float v0 = whb[(size_t)jlist[k] * C_];
        float v1 = (k + 1 < n) ? whb[(size_t)jlist[k + 1] * C_] : 0.f;
        float v2 = (k + 2 < n) ? whb[(size_t)jlist[k + 2] * C_] : 0.f;
        float v3 = (k + 3 < n) ? whb[(size_t)jlist[k + 3] * C_] : 0.f;
        corr += (v0 + v1) + (v2 + v3);
    }
    float fout = lrelu((S - corr) * (1.0f / V_));
    float fin  = lrelu(sdeg * whb[(size_t)i * C_]);
    int g = c >> 6, o = c & 63;
    size_t oidx = (((size_t)b * G_ + g) * V_ + i) * FOUT_ + o;
    g_featin[oidx]  = fin;
    g_featout[oidx] = fout;
}

// ---------------- K4: 5x5 conv via row-Winograd F(2,5) ----------------
// grid (V/8, B, 2), block 256 = cg(8) x tile(4) x g(8). Block: 8 output rows
// (4 tiles x 2), 64 cols, 8 g. m rows padded to 72 floats, chunk-XOR swizzled
// (bank-conflict-free LDS.128 phases). MACs/output: 200 -> 120.
#define MW_ 72
#define RAW_OFF 0
#define M_OFF   6144
#define U_OFF   (6144 + 8*4*6*MW_)          // 19968
#define SB_OFF  (U_OFF + 3072)              // 23040
#define CONV_SMEM ((23040 + 16) * 4)

__device__ __forceinline__ int swz(int c) { return c ^ ((c >> 3) & 1); }

__global__ void __launch_bounds__(256, 2) k_conv(const float* __restrict__ cw1,
                                                 const float* __restrict__ cb1,
                                                 const float* __restrict__ cw2,
                                                 const float* __restrict__ cb2,
                                                 float* __restrict__ out) {
    extern __shared__ float s[];
    float* raw = s + RAW_OFF;     // [cin][12][64]
    float* sm  = s + M_OFF;       // [cin][tile4][i6][72] swizzled
    float* sU  = s + U_OFF;       // [g][cin][i6][8]
    float* sb  = s + SB_OFF;

    int which = blockIdx.z;
    int b = blockIdx.y;
    int r0 = blockIdx.x * 8;
    int t = threadIdx.x;

    const float* feat = which ? g_featout : g_featin;
    const float* cw   = which ? cw2 : cw1;
    const float* cb   = which ? cb2 : cb1;

    if (t < 8) sb[t] = cb[t];

    // A1: stage raw rows r0-2 .. r0+9
#pragma unroll 1
    for (int q = t; q < 1536; q += 256) {
        int cin = q / 192;
        int rem = q - cin * 192;
        int row = rem >> 4;
        int c4  = rem & 15;
        int v = r0 - 2 + row;
        float4 val = make_float4(0.f, 0.f, 0.f, 0.f);
        if (v >= 0 && v < V_)
            val = *(const float4*)(feat + (((size_t)b * G_ + cin) * V_ + v) * FOUT_ + c4 * 4);
        *(float4*)(raw + (cin * 12 + row) * 64 + c4 * 4) = val;
    }
    // zero-fill m pad chunks (cols 64..71 of every m row)
    for (int q = t; q < 1536; q += 256)
        sm[(q >> 3) * MW_ + 64 + (q & 7)] = 0.f;
    // A2: U[g][cin][i][kw] = sum_kh G[i][kh] * w[g][cin][kh][kw]
#pragma unroll 1
    for (int q = t; q < 384; q += 256) {
        int g = q / 48;
        int rem = q - g * 48;
        int cin = rem / 6;
        int i = rem - cin * 6;
        const float* wp = cw + (g * 8 + cin) * 25;
        float* up = sU + ((g * 8 + cin) * 6 + i) * 8;
#pragma unroll
        for (int kw = 0; kw < 5; kw++)
            up[kw] = c_G[i][0] * wp[kw] + c_G[i][1] * wp[5 + kw] + c_G[i][2] * wp[10 + kw]
                   + c_G[i][3] * wp[15 + kw] + c_G[i][4] * wp[20 + kw];
    }
    __syncthreads();

    // A3: data transform m = B^T d, swizzled store
#pragma unroll 1
    for (int q = t; q < 2048; q += 256) {
        int col  = q & 63;
        int tile = (q >> 6) & 3;
        int cin  = q >> 8;
        const float* rp = raw + (cin * 12 + 2 * tile) * 64 + col;
        float d0 = rp[0], d1 = rp[64], d2 = rp[128], d3 = rp[192], d4 = rp[256], d5 = rp[320];
        float* mp = sm + (cin * 4 + tile) * 6 * MW_ + swz(col >> 2) * 4 + (col & 3);
        mp[0]      = 4.f * d0 - 5.f * d2 + d4;
        mp[MW_]    = -4.f * d1 - 4.f * d2 + d3 + d4;
        mp[2*MW_]  =  4.f * d1 - 4.f * d2 - d3 + d4;
        mp[3*MW_]  = -2.f * d1 - d2 + 2.f * d3 + d4;
        mp[4*MW_]  =  2.f * d1 - d2 - 2.f * d3 + d4;
        mp[5*MW_]  =  4.f * d1 - 5.f * d3 + d5;
    }
    __syncthreads();

    // B: M accumulation + incremental inverse transform
    int cg = t & 7, tile = (t >> 3) & 3, g = t >> 5;
    int w0 = cg * 8;
    int p0 = swz(2 * cg) * 4, p1 = swz(2 * cg + 1) * 4, p2 = swz(2 * cg + 2) * 4;

    float bias = sb[g];
    float out0[8], out1[8];
#pragma unroll
    for (int w = 0; w < 8; w++) { out0[w] = bias; out1[w] = bias; }

    const float a0c[6] = {1.f, 1.f, 1.f, 1.f, 1.f, 0.f};
    const float a1c[6] = {0.f, 1.f, -1.f, 2.f, -2.f, 1.f};

#pragma unroll 1
    for (int i = 0; i < 6; i++) {
        float Mi[8] = {0.f, 0.f, 0.f, 0.f, 0.f, 0.f, 0.f, 0.f};
#pragma unroll
        for (int cin = 0; cin < 8; cin++) {
            const float* mp = sm + ((cin * 4 + tile) * 6 + i) * MW_;
            float4 ma = *(const float4*)(mp + p0);
            float4 mb = *(const float4*)(mp + p1);
            float4 mc = *(const float4*)(mp + p2);
            float mr[12] = {ma.x, ma.y, ma.z, ma.w, mb.x, mb.y, mb.z, mb.w,
                            mc.x, mc.y, mc.z, mc.w};
            const float* up = sU + ((g * 8 + cin) * 6 + i) * 8;
            float u0 = up[0], u1 = up[1], u2 = up[2], u3 = up[3], u4 = up[4];
#pragma unroll
            for (int w = 0; w < 8; w++)
                Mi[w] += mr[w] * u0 + mr[w + 1] * u1 + mr[w + 2] * u2
                       + mr[w + 3] * u3 + mr[w + 4] * u4;
        }
        float a0 = a0c[i], a1 = a1c[i];
#pragma unroll
        for (int w = 0; w < 8; w++) {
            out0[w] += a0 * Mi[w];
            out1[w] += a1 * Mi[w];
        }
    }

    int v0 = r0 + 2 * tile;
    size_t base = (((size_t)b * G_ + g) * V_ + v0) * OUTC_ + which * OUTW_ + w0;
    *(float4*)(out + base)         = make_float4(out0[0], out0[1], out0[2], out0[3]);
    *(float4*)(out + base + OUTC_) = make_float4(out1[0], out1[1], out1[2], out1[3]);
    if (cg < 7) {
        *(float4*)(out + base + 4)         = make_float4(out0[4], out0[5], out0[6], out0[7]);
        *(float4*)(out + base + OUTC_ + 4) = make_float4(out1[4], out1[5], out1[6], out1[7]);
    }
}

// ---------------- launch ----------------
extern "C" void kernel_launch(void* const* d_in, const int* in_sizes, int n_in,
                              void* d_out, int out_size) {
    const float* h       = (const float*)d_in[0];
    const int*   adj     = (const int*)d_in[1];
    const float* W       = (const float*)d_in[2];
    const float* conv1_w = (const float*)d_in[3];
    const float* conv1_b = (const float*)d_in[4];
    const float* conv2_w = (const float*)d_in[5];
    const float* conv2_b = (const float*)d_in[6];
    float* out = (float*)d_out;

    static cudaStream_t s1 = nullptr;
    static cudaEvent_t ev0 = nullptr, ev1 = nullptr;
    if (s1 == nullptr) {
        cudaStreamCreateWithFlags(&s1, cudaStreamNonBlocking);
        cudaEventCreateWithFlags(&ev0, cudaEventDisableTiming);
        cudaEventCreateWithFlags(&ev1, cudaEventDisableTiming);
        cudaFuncSetAttribute(k_conv, cudaFuncAttributeMaxDynamicSharedMemorySize, CONV_SMEM);
    }

    k_zero<<<8, 1024>>>();
    cudaEventRecord(ev0, 0);
    cudaStreamWaitEvent(s1, ev0, 0);

    k_adj<<<dim3(V_, B_), 256>>>(adj);
    k_wh<<<dim3(16, G_, B_), 256, 0, s1>>>(h, W);
    k_sreduce<<<64, 64, 0, s1>>>();

    cudaEventRecord(ev1, s1);
    cudaStreamWaitEvent(0, ev1, 0);

    k_feat<<<dim3(V_, B_), 512>>>();
    k_conv<<<dim3(V_ / 8, B_, 2), 256, CONV_SMEM>>>(conv1_w, conv1_b, conv2_w, conv2_b, out);
}

// round 9
// speedup vs baseline: 1.0350x; 1.0350x over previous
#include <cuda_runtime.h>

#define ALPHA 0.2f
#define B_   8
#define G_   8
#define V_   1024
#define FOUT_ 64
#define C_   512
#define OUTW_ 60
#define OUTC_ 120

// ---------------- scratch ----------------
__device__ __align__(16) float    g_Wh[B_*V_*C_];
__device__ float                  g_Spart[B_*16*C_];
__device__ float                  g_S[B_*C_];
__device__ unsigned               g_rowmask[B_*V_*32];
__device__ int                    g_zcol[B_*V_];
__device__ __align__(16) float    g_featin[B_*G_*V_*FOUT_];
__device__ __align__(16) float    g_featout[B_*G_*V_*FOUT_];

__device__ __forceinline__ float lrelu(float x) { return x >= 0.f ? x : ALPHA * x; }

// Winograd F(2,5) filter transform G' (6x5), points {0,1,-1,2,-2,inf}
__device__ const float c_G[6][5] = {
    { 0.25f, 0.f, 0.f, 0.f, 0.f },
    {-1.f/6.f, -1.f/6.f, -1.f/6.f, -1.f/6.f, -1.f/6.f },
    {-1.f/6.f,  1.f/6.f, -1.f/6.f,  1.f/6.f, -1.f/6.f },
    { 1.f/24.f, 2.f/24.f, 4.f/24.f, 8.f/24.f, 16.f/24.f },
    { 1.f/24.f,-2.f/24.f, 4.f/24.f,-8.f/24.f, 16.f/24.f },
    { 0.f, 0.f, 0.f, 0.f, 1.f }
};

__global__ void k_zero() {
    int t = blockIdx.x * blockDim.x + threadIdx.x;
    if (t < B_ * V_) g_zcol[t] = 0;
}

__global__ void __launch_bounds__(256) k_adj(const int* __restrict__ adj) {
    int i = blockIdx.x, b = blockIdx.y;
    __shared__ unsigned mask[32];
    int t = threadIdx.x;
    if (t < 32) mask[t] = 0u;
    __syncthreads();
    const int4* p = (const int4*)(adj + (size_t)b * G_ * V_ * V_ + (size_t)i * V_);
    int4 acc = p[t];
#pragma unroll
    for (int g = 1; g < G_; g++) {
        int4 v = p[(size_t)g * (V_ * (V_ / 4)) + t];
        acc.x |= v.x; acc.y |= v.y; acc.z |= v.z; acc.w |= v.w;
    }
    unsigned nib = (unsigned)(acc.x == 0) | ((unsigned)(acc.y == 0) << 1) |
                   ((unsigned)(acc.z == 0) << 2) | ((unsigned)(acc.w == 0) << 3);
    if (nib) {
        atomicOr(&mask[t >> 3], nib << ((t & 7) * 4));
        int jb = b * V_ + 4 * t;
        if (acc.x == 0) atomicAdd(&g_zcol[jb + 0], 1);
        if (acc.y == 0) atomicAdd(&g_zcol[jb + 1], 1);
        if (acc.z == 0) atomicAdd(&g_zcol[jb + 2], 1);
        if (acc.w == 0) atomicAdd(&g_zcol[jb + 3], 1);
    }
    __syncthreads();
    if (t < 32) g_rowmask[((size_t)b * V_ + i) * 32 + t] = mask[t];
}

__global__ void __launch_bounds__(256) k_wh(const float* __restrict__ h,
                                            const float* __restrict__ W) {
    __shared__ __align__(16) float sW[64 * 64];
    __shared__ __align__(16) float sH[64 * 64];
    __shared__ float red[64 * 17];
    int t = threadIdx.x;
    int vt = blockIdx.x, g = blockIdx.y, b = blockIdx.z;
    const float4* wp = (const float4*)(W + (size_t)g * 4096);
    const float4* hp = (const float4*)(h + (((size_t)b * G_ + g) * V_ + (size_t)vt * 64) * 64);
    float4* sw4 = (float4*)sW;
    float4* sh4 = (float4*)sH;
#pragma unroll
    for (int q = t; q < 1024; q += 256) { sw4[q] = wp[q]; sh4[q] = hp[q]; }
    __syncthreads();
    int tx = t & 15, ty = t >> 4;
    int o0 = tx * 4, r0 = ty * 4;
    float acc[4][4] = {};
#pragma unroll 4
    for (int i = 0; i < 64; i++) {
        float4 bb = *(const float4*)(sW + i * 64 + o0);
#pragma unroll
        for (int r = 0; r < 4; r++) {
            float a = sH[(r0 + r) * 64 + i];
            acc[r][0] += a * bb.x; acc[r][1] += a * bb.y;
            acc[r][2] += a * bb.z; acc[r][3] += a * bb.w;
        }
    }
    float cs[4] = {0.f, 0.f, 0.f, 0.f};
#pragma unroll
    for (int r = 0; r < 4; r++) {
        float4 v;
        v.x = lrelu(acc[r][0]); v.y = lrelu(acc[r][1]);
        v.z = lrelu(acc[r][2]); v.w = lrelu(acc[r][3]);
        size_t row = (size_t)b * V_ + vt * 64 + r0 + r;
        *(float4*)(g_Wh + row * C_ + g * 64 + o0) = v;
        cs[0] += v.x; cs[1] += v.y; cs[2] += v.z; cs[3] += v.w;
    }
    __syncthreads();
#pragma unroll
    for (int j = 0; j < 4; j++) red[(o0 + j) * 17 + ty] = cs[j];
    __syncthreads();
    if (t < 64) {
        float s = 0.f;
#pragma unroll
        for (int k = 0; k < 16; k++) s += red[t * 17 + k];
        g_Spart[((size_t)b * 16 + vt) * C_ + g * 64 + t] = s;
    }
}

__global__ void k_sreduce() {
    int b = blockIdx.x >> 3;
    int c = (blockIdx.x & 7) * 64 + threadIdx.x;
    float s = 0.f;
#pragma unroll
    for (int vt = 0; vt < 16; vt++) s += g_Spart[((size_t)b * 16 + vt) * C_ + c];
    g_S[b * C_ + c] = s;
}

__global__ void __launch_bounds__(512) k_feat() {
    int i = blockIdx.x, b = blockIdx.y;
    int c = threadIdx.x;
    __shared__ short jlist[64];
    __shared__ int njs;
    __shared__ float sdeg;
    if (c == 0) sdeg = (float)(V_ - g_zcol[b * V_ + i]) * (1.0f / V_);
    if (c < 32) {
        unsigned mw = g_rowmask[((size_t)b * V_ + i) * 32 + c];
        int cnt = __popc(mw);
        int pre = cnt;
#pragma unroll
        for (int d = 1; d < 32; d <<= 1) {
            int v = __shfl_up_sync(0xffffffffu, pre, d);
            if (c >= d) pre += v;
        }
        int excl = pre - cnt;
        if (c == 31) njs = pre;
        while (mw) {
            int p = __ffs(mw) - 1;
            mw &= mw - 1;
            jlist[excl++] = (short)(c * 32 + p);
        }
    }
    __syncthreads();
    float S = g_S[b * C_ + c];
    float corr = 0.f;
    int n = njs;
    const float* whb = g_Wh + (size_t)b * V_ * C_ + c;
#pragma unroll 1
    for (int k = 0; k < n; k += 4) {
        float v0 = whb[(size_t)jlist[k] * C_];
        float v1 = (k + 1 < n) ? whb[(size_t)jlist[k + 1] * C_] : 0.f;
        float v2 = (k + 2 < n) ? whb[(size_t)jlist[k + 2] * C_] : 0.f;
        float v3 = (k + 3 < n) ? whb[(size_t)jlist[k + 3] * C_] : 0.f;
        corr += (v0 + v1) + (v2 + v3);
    }
    float fout = lrelu((S - corr) * (1.0f / V_));
    float fin  = lrelu(sdeg * whb[(size_t)i * C_]);
    int g = c >> 6, o = c & 63;
    size_t oidx = (((size_t)b * G_ + g) * V_ + i) * FOUT_ + o;
    g_featin[oidx]  = fin;
    g_featout[oidx] = fout;
}

// ---------------- K4: 5x5 conv via row-Winograd F(2,5), v2 ----------------
// grid (V/8, B, 2), block 256 = cg(8) x tile(4) x g(8). No raw staging: the
// data transform reads feat straight from gmem (L2-resident). Smem 67KB ->
// 3 CTAs/SM. U reads 2 LDS instead of 5. MACs/output: 120 (direct: 200).
#define MW_ 72
#define M_FLOATS (8*4*6*MW_)                 // 13824
#define U_OFF    M_FLOATS
#define SB_OFF   (M_FLOATS + 3072)           // 16896
#define CONV_SMEM ((16896 + 16) * 4)

__device__ __forceinline__ int swz(int c) { return c ^ ((c >> 3) & 1); }

__global__ void __launch_bounds__(256, 3) k_conv(const float* __restrict__ cw1,
                                                 const float* __restrict__ cb1,
                                                 const float* __restrict__ cw2,
                                                 const float* __restrict__ cb2,
                                                 float* __restrict__ out) {
    extern __shared__ float s[];
    float* sm  = s;               // [cin][tile4][i6][72] swizzled
    float* sU  = s + U_OFF;       // [g][cin][i6][8]
    float* sb  = s + SB_OFF;

    int which = blockIdx.z;
    int b = blockIdx.y;
    int r0 = blockIdx.x * 8;
    int t = threadIdx.x;

    const float* feat = which ? g_featout : g_featin;
    const float* cw   = which ? cw2 : cw1;
    const float* cb   = which ? cb2 : cb1;

    if (t < 8) sb[t] = cb[t];

    // zero-fill m pad chunks (cols 64..71 of all 192 m rows)
    for (int q = t; q < 1536; q += 256)
        sm[(q >> 3) * MW_ + 64 + (q & 7)] = 0.f;

    // U[g][cin][i][kw] = sum_kh G[i][kh] * w[g][cin][kh][kw]
#pragma unroll 1
    for (int q = t; q < 384; q += 256) {
        int g = q / 48;
        int rem = q - g * 48;
        int cin = rem / 6;
        int i = rem - cin * 6;
        const float* wp = cw + (g * 8 + cin) * 25;
        float* up = sU + ((g * 8 + cin) * 6 + i) * 8;
#pragma unroll
        for (int kw = 0; kw < 5; kw++)
            up[kw] = c_G[i][0] * wp[kw] + c_G[i][1] * wp[5 + kw] + c_G[i][2] * wp[10 + kw]
                   + c_G[i][3] * wp[15 + kw] + c_G[i][4] * wp[20 + kw];
        up[5] = 0.f; up[6] = 0.f; up[7] = 0.f;
    }

    // data transform m = B^T d, direct from gmem, swizzled store
#pragma unroll 1
    for (int q = t; q < 2048; q += 256) {
        int col  = q & 63;
        int tile = (q >> 6) & 3;
        int cin  = q >> 8;
        int vbase = r0 - 2 + 2 * tile;
        const float* fp = feat + ((size_t)b * G_ + cin) * V_ * 64 + col;
        float d[6];
#pragma unroll
        for (int k = 0; k < 6; k++) {
            int v = vbase + k;
            d[k] = (v >= 0 && v < V_) ? fp[(size_t)v * 64] : 0.f;
        }
        float* mp = sm + (cin * 4 + tile) * 6 * MW_ + swz(col >> 2) * 4 + (col & 3);
        mp[0]      = 4.f * d[0] - 5.f * d[2] + d[4];
        mp[MW_]    = -4.f * d[1] - 4.f * d[2] + d[3] + d[4];
        mp[2*MW_]  =  4.f * d[1] - 4.f * d[2] - d[3] + d[4];
        mp[3*MW_]  = -2.f * d[1] - d[2] + 2.f * d[3] + d[4];
        mp[4*MW_]  =  2.f * d[1] - d[2] - 2.f * d[3] + d[4];
        mp[5*MW_]  =  4.f * d[1] - 5.f * d[3] + d[5];
    }
    __syncthreads();

    // B: M accumulation + incremental inverse transform
    int cg = t & 7, tile = (t >> 3) & 3, g = t >> 5;
    int w0 = cg * 8;
    int p0 = swz(2 * cg) * 4, p1 = swz(2 * cg + 1) * 4, p2 = swz(2 * cg + 2) * 4;

    float bias = sb[g];
    float out0[8], out1[8];
#pragma unroll
    for (int w = 0; w < 8; w++) { out0[w] = bias; out1[w] = bias; }

    const float a0c[6] = {1.f, 1.f, 1.f, 1.f, 1.f, 0.f};
    const float a1c[6] = {0.f, 1.f, -1.f, 2.f, -2.f, 1.f};

#pragma unroll 1
    for (int i = 0; i < 6; i++) {
        float Mi[8] = {0.f, 0.f, 0.f, 0.f, 0.f, 0.f, 0.f, 0.f};
#pragma unroll
        for (int cin = 0; cin < 8; cin++) {
            const float* mp = sm + ((cin * 4 + tile) * 6 + i) * MW_;
            float4 ma = *(const float4*)(mp + p0);
            float4 mb = *(const float4*)(mp + p1);
            float4 mc = *(const float4*)(mp + p2);
            float mr[12] = {ma.x, ma.y, ma.z, ma.w, mb.x, mb.y, mb.z, mb.w,
                            mc.x, mc.y, mc.z, mc.w};
            const float* up = sU + ((g * 8 + cin) * 6 + i) * 8;
            float4 uu = *(const float4*)up;
            float u4 = up[4];
#pragma unroll
            for (int w = 0; w < 8; w++)
                Mi[w] += mr[w] * uu.x + mr[w + 1] * uu.y + mr[w + 2] * uu.z
                       + mr[w + 3] * uu.w + mr[w + 4] * u4;
        }
        float a0 = a0c[i], a1 = a1c[i];
#pragma unroll
        for (int w = 0; w < 8; w++) {
            out0[w] += a0 * Mi[w];
            out1[w] += a1 * Mi[w];
        }
    }

    int v0 = r0 + 2 * tile;
    size_t base = (((size_t)b * G_ + g) * V_ + v0) * OUTC_ + which * OUTW_ + w0;
    *(float4*)(out + base)         = make_float4(out0[0], out0[1], out0[2], out0[3]);
    *(float4*)(out + base + OUTC_) = make_float4(out1[0], out1[1], out1[2], out1[3]);
    if (cg < 7) {
        *(float4*)(out + base + 4)         = make_float4(out0[4], out0[5], out0[6], out0[7]);
        *(float4*)(out + base + OUTC_ + 4) = make_float4(out1[4], out1[5], out1[6], out1[7]);
    }
}

// ---------------- launch ----------------
extern "C" void kernel_launch(void* const* d_in, const int* in_sizes, int n_in,
                              void* d_out, int out_size) {
    const float* h       = (const float*)d_in[0];
    const int*   adj     = (const int*)d_in[1];
    const float* W       = (const float*)d_in[2];
    const float* conv1_w = (const float*)d_in[3];
    const float* conv1_b = (const float*)d_in[4];
    const float* conv2_w = (const float*)d_in[5];
    const float* conv2_b = (const float*)d_in[6];
    float* out = (float*)d_out;

    static cudaStream_t s1 = nullptr;
    static cudaEvent_t ev0 = nullptr, ev1 = nullptr;
    if (s1 == nullptr) {
        cudaStreamCreateWithFlags(&s1, cudaStreamNonBlocking);
        cudaEventCreateWithFlags(&ev0, cudaEventDisableTiming);
        cudaEventCreateWithFlags(&ev1, cudaEventDisableTiming);
        cudaFuncSetAttribute(k_conv, cudaFuncAttributeMaxDynamicSharedMemorySize, CONV_SMEM);
    }

    k_zero<<<8, 1024>>>();
    cudaEventRecord(ev0, 0);
    cudaStreamWaitEvent(s1, ev0, 0);

    k_adj<<<dim3(V_, B_), 256>>>(adj);
    k_wh<<<dim3(16, G_, B_), 256, 0, s1>>>(h, W);
    k_sreduce<<<64, 64, 0, s1>>>();

    cudaEventRecord(ev1, s1);
    cudaStreamWaitEvent(0, ev1, 0);

    k_feat<<<dim3(V_, B_), 512>>>();
    k_conv<<<dim3(V_ / 8, B_, 2), 256, CONV_SMEM>>>(conv1_w, conv1_b, conv2_w, conv2_b, out);
}

// round 11
// speedup vs baseline: 1.1185x; 1.0807x over previous
#include <cuda_runtime.h>

#define ALPHA 0.2f
#define B_   8
#define G_   8
#define V_   1024
#define FOUT_ 64
#define C_   512
#define OUTW_ 60
#define OUTC_ 120

typedef unsigned long long ull;

// ---------------- scratch ----------------
__device__ __align__(16) float    g_Wh[B_*V_*C_];
__device__ float                  g_Spart[B_*16*C_];
__device__ float                  g_S[B_*C_];
__device__ unsigned               g_rowmask[B_*V_*32];
__device__ int                    g_zcol[B_*V_];        // zeroed at load; re-zeroed each replay after use
__device__ __align__(16) float    g_featin[B_*G_*V_*FOUT_];
__device__ __align__(16) float    g_featout[B_*G_*V_*FOUT_];

__device__ __forceinline__ float lrelu(float x) { return x >= 0.f ? x : ALPHA * x; }

__device__ __forceinline__ ull pack2(float x, float y) {
    ull r; asm("mov.b64 %0, {%1, %2};" : "=l"(r) : "f"(x), "f"(y)); return r;
}
__device__ __forceinline__ ull bcast2(float x) {
    ull r; asm("mov.b64 %0, {%1, %1};" : "=l"(r) : "f"(x)); return r;
}
__device__ __forceinline__ ull fma2(ull a, ull b, ull c) {
    ull d; asm("fma.rn.f32x2 %0, %1, %2, %3;" : "=l"(d) : "l"(a), "l"(b), "l"(c)); return d;
}
__device__ __forceinline__ float2 unpack2(ull v) {
    float2 r; asm("mov.b64 {%0, %1}, %2;" : "=f"(r.x), "=f"(r.y) : "l"(v)); return r;
}

__global__ void k_zero() {
    int t = blockIdx.x * blockDim.x + threadIdx.x;
    if (t < B_ * V_) g_zcol[t] = 0;
}

// ---------------- adj scan ----------------
__global__ void __launch_bounds__(256) k_adj(const int* __restrict__ adj) {
    int i = blockIdx.x, b = blockIdx.y;
    __shared__ unsigned mask[32];
    int t = threadIdx.x;
    if (t < 32) mask[t] = 0u;
    __syncthreads();
    const int4* p = (const int4*)(adj + (size_t)b * G_ * V_ * V_ + (size_t)i * V_);
    int4 acc = p[t];
#pragma unroll
    for (int g = 1; g < G_; g++) {
        int4 v = p[(size_t)g * (V_ * (V_ / 4)) + t];
        acc.x |= v.x; acc.y |= v.y; acc.z |= v.z; acc.w |= v.w;
    }
    unsigned nib = (unsigned)(acc.x == 0) | ((unsigned)(acc.y == 0) << 1) |
                   ((unsigned)(acc.z == 0) << 2) | ((unsigned)(acc.w == 0) << 3);
    if (nib) {
        atomicOr(&mask[t >> 3], nib << ((t & 7) * 4));
        int jb = b * V_ + 4 * t;
        if (acc.x == 0) atomicAdd(&g_zcol[jb + 0], 1);
        if (acc.y == 0) atomicAdd(&g_zcol[jb + 1], 1);
        if (acc.z == 0) atomicAdd(&g_zcol[jb + 2], 1);
        if (acc.w == 0) atomicAdd(&g_zcol[jb + 3], 1);
    }
    __syncthreads();
    if (t < 32) g_rowmask[((size_t)b * V_ + i) * 32 + t] = mask[t];
}

// ---------------- Wh GEMM ----------------
__global__ void __launch_bounds__(256) k_wh(const float* __restrict__ h,
                                            const float* __restrict__ W) {
    __shared__ __align__(16) float sW[64 * 64];
    __shared__ __align__(16) float sH[64 * 64];
    __shared__ float red[64 * 17];
    int t = threadIdx.x;
    int vt = blockIdx.x, g = blockIdx.y, b = blockIdx.z;
    const float4* wp = (const float4*)(W + (size_t)g * 4096);
    const float4* hp = (const float4*)(h + (((size_t)b * G_ + g) * V_ + (size_t)vt * 64) * 64);
    float4* sw4 = (float4*)sW;
    float4* sh4 = (float4*)sH;
#pragma unroll
    for (int q = t; q < 1024; q += 256) { sw4[q] = wp[q]; sh4[q] = hp[q]; }
    __syncthreads();
    int tx = t & 15, ty = t >> 4;
    int o0 = tx * 4, r0 = ty * 4;
    float acc[4][4] = {};
#pragma unroll 4
    for (int i = 0; i < 64; i++) {
        float4 bb = *(const float4*)(sW + i * 64 + o0);
#pragma unroll
        for (int r = 0; r < 4; r++) {
            float a = sH[(r0 + r) * 64 + i];
            acc[r][0] += a * bb.x; acc[r][1] += a * bb.y;
            acc[r][2] += a * bb.z; acc[r][3] += a * bb.w;
        }
    }
    float cs[4] = {0.f, 0.f, 0.f, 0.f};
#pragma unroll
    for (int r = 0; r < 4; r++) {
        float4 v;
        v.x = lrelu(acc[r][0]); v.y = lrelu(acc[r][1]);
        v.z = lrelu(acc[r][2]); v.w = lrelu(acc[r][3]);
        size_t row = (size_t)b * V_ + vt * 64 + r0 + r;
        *(float4*)(g_Wh + row * C_ + g * 64 + o0) = v;
        cs[0] += v.x; cs[1] += v.y; cs[2] += v.z; cs[3] += v.w;
    }
    __syncthreads();
#pragma unroll
    for (int j = 0; j < 4; j++) red[(o0 + j) * 17 + ty] = cs[j];
    __syncthreads();
    if (t < 64) {
        float s = 0.f;
#pragma unroll
        for (int k = 0; k < 16; k++) s += red[t * 17 + k];
        g_Spart[((size_t)b * 16 + vt) * C_ + g * 64 + t] = s;
    }
}

__global__ void k_sreduce() {
    int b = blockIdx.x >> 3;
    int c = (blockIdx.x & 7) * 64 + threadIdx.x;
    float s = 0.f;
#pragma unroll
    for (int vt = 0; vt < 16; vt++) s += g_Spart[((size_t)b * 16 + vt) * C_ + c];
    g_S[b * C_ + c] = s;
}

// ---------------- featin: fin = lrelu(deg * Wh) ----------------
__global__ void __launch_bounds__(512) k_featin() {
    int i = blockIdx.x, b = blockIdx.y;
    int c = threadIdx.x;
    float sdeg = (float)(V_ - g_zcol[b * V_ + i]) * (1.0f / V_);
    float fin = lrelu(sdeg * g_Wh[((size_t)b * V_ + i) * C_ + c]);
    int g = c >> 6, o = c & 63;
    g_featin[(((size_t)b * G_ + g) * V_ + i) * FOUT_ + o] = fin;
}

// ---------------- featout: fout = lrelu((S - corr)/V) ----------------
__global__ void __launch_bounds__(512) k_featout() {
    int i = blockIdx.x, b = blockIdx.y;
    int c = threadIdx.x;
    __shared__ short jlist[64];
    __shared__ int njs;
    if (c < 32) {
        unsigned mw = g_rowmask[((size_t)b * V_ + i) * 32 + c];
        int cnt = __popc(mw);
        int pre = cnt;
#pragma unroll
        for (int d = 1; d < 32; d <<= 1) {
            int v = __shfl_up_sync(0xffffffffu, pre, d);
            if (c >= d) pre += v;
        }
        int excl = pre - cnt;
        if (c == 31) njs = pre;
        while (mw) {
            int p = __ffs(mw) - 1;
            mw &= mw - 1;
            jlist[excl++] = (short)(c * 32 + p);
        }
    }
    __syncthreads();
    float S = g_S[b * C_ + c];
    float corr = 0.f;
    int n = njs;
    const float* whb = g_Wh + (size_t)b * V_ * C_ + c;
#pragma unroll 1
    for (int k = 0; k < n; k += 4) {
        float v0 = whb[(size_t)jlist[k] * C_];
        float v1 = (k + 1 < n) ? whb[(size_t)jlist[k + 1] * C_] : 0.f;
        float v2 = (k + 2 < n) ? whb[(size_t)jlist[k + 2] * C_] : 0.f;
        float v3 = (k + 3 < n) ? whb[(size_t)jlist[k + 3] * C_] : 0.f;
        corr += (v0 + v1) + (v2 + v3);
    }
    float fout = lrelu((S - corr) * (1.0f / V_));
    int g = c >> 6, o = c & 63;
    g_featout[(((size_t)b * G_ + g) * V_ + i) * FOUT_ + o] = fout;
}

// ---------------- conv (R2-proven direct); which selects plane/cols ----------
__global__ void __launch_bounds__(512) k_conv(const float* __restrict__ cw,
                                              const float* __restrict__ cb,
                                              float* __restrict__ out,
                                              int which) {
    int b = blockIdx.y;
    int r0 = blockIdx.x * 16;
    int coloff = which ? OUTW_ : 0;

    __shared__ __align__(16) float sin_[8][20][64];
    __shared__ __align__(8) float2 swt2[4 * 8 * 25];
    __shared__ float2 sb2[4];

    const float* feat = which ? g_featout : g_featin;

    int t = threadIdx.x;
    for (int q = t; q < 800; q += 512) {
        int gg = q / 200;
        int rem = q - gg * 200;
        swt2[q] = make_float2(cw[(2 * gg) * 200 + rem], cw[(2 * gg + 1) * 200 + rem]);
    }
    if (t < 4) sb2[t] = make_float2(cb[2 * t], cb[2 * t + 1]);

#pragma unroll
    for (int q = t; q < 2560; q += 512) {
        int cin = q / 320;
        int rem = q - cin * 320;
        int row = rem >> 4;
        int o4  = rem & 15;
        int v = r0 - 2 + row;
        float4 val = make_float4(0.f, 0.f, 0.f, 0.f);
        if (v >= 0 && v < V_)
            val = *(const float4*)(feat + (((size_t)b * G_ + cin) * V_ + v) * FOUT_ + o4 * 4);
        *(float4*)(&sin_[cin][row][o4 * 4]) = val;
    }
    __syncthreads();

    int cg = t & 15, rg = (t >> 4) & 7, gg = t >> 7;
    if (cg < 15) {
        int w0 = cg * 4;
        int lr = rg * 2;

        ull bias = pack2(sb2[gg].x, sb2[gg].y);
        ull acc[2][4];
#pragma unroll
        for (int r = 0; r < 2; r++)
#pragma unroll
            for (int c = 0; c < 4; c++) acc[r][c] = bias;

        const float2* wp = &swt2[gg * 200];

#pragma unroll 1
        for (int cin = 0; cin < 8; cin++) {
#pragma unroll
            for (int kh = 0; kh < 5; kh++) {
                ull in2[2][8];
#pragma unroll
                for (int rr = 0; rr < 2; rr++) {
                    float4 a4 = *(const float4*)(&sin_[cin][lr + kh + rr][w0]);
                    float4 b4 = *(const float4*)(&sin_[cin][lr + kh + rr][w0 + 4]);
                    in2[rr][0] = bcast2(a4.x); in2[rr][1] = bcast2(a4.y);
                    in2[rr][2] = bcast2(a4.z); in2[rr][3] = bcast2(a4.w);
                    in2[rr][4] = bcast2(b4.x); in2[rr][5] = bcast2(b4.y);
                    in2[rr][6] = bcast2(b4.z); in2[rr][7] = bcast2(b4.w);
                }
#pragma unroll
                for (int kw = 0; kw < 5; kw++) {
                    float2 w2 = wp[cin * 25 + kh * 5 + kw];
                    ull wt = pack2(w2.x, w2.y);
#pragma unroll
                    for (int r = 0; r < 2; r++) {
#pragma unroll
                        for (int c = 0; c < 4; c++)
                            acc[r][c] = fma2(in2[r][kw + c], wt, acc[r][c]);
                    }
                }
            }
        }

#pragma unroll
        for (int r = 0; r < 2; r++) {
            float2 u0 = unpack2(acc[r][0]);
            float2 u1 = unpack2(acc[r][1]);
            float2 u2 = unpack2(acc[r][2]);
            float2 u3 = unpack2(acc[r][3]);
            int v = r0 + lr + r;
            size_t base0 = (((size_t)b * G_ + (2 * gg)) * V_ + v) * OUTC_ + coloff + w0;
            size_t base1 = (((size_t)b * G_ + (2 * gg + 1)) * V_ + v) * OUTC_ + coloff + w0;
            *(float4*)(out + base0) = make_float4(u0.x, u1.x, u2.x, u3.x);
            *(float4*)(out + base1) = make_float4(u0.y, u1.y, u2.y, u3.y);
        }
    }
}

// ---------------- launch: two-stream pipeline ----------------
extern "C" void kernel_launch(void* const* d_in, const int* in_sizes, int n_in,
                              void* d_out, int out_size) {
    const float* h       = (const float*)d_in[0];
    const int*   adj     = (const int*)d_in[1];
    const float* W       = (const float*)d_in[2];
    const float* conv1_w = (const float*)d_in[3];
    const float* conv1_b = (const float*)d_in[4];
    const float* conv2_w = (const float*)d_in[5];
    const float* conv2_b = (const float*)d_in[6];
    float* out = (float*)d_out;

    static cudaStream_t s1 = nullptr;
    static cudaEvent_t evA = nullptr, evS = nullptr, evD = nullptr;
    if (s1 == nullptr) {
        cudaStreamCreateWithFlags(&s1, cudaStreamNonBlocking);
        cudaEventCreateWithFlags(&evA, cudaEventDisableTiming);
        cudaEventCreateWithFlags(&evS, cudaEventDisableTiming);
        cudaEventCreateWithFlags(&evD, cudaEventDisableTiming);
    }

    // fork s1 from legacy at entry
    cudaEventRecord(evD, 0);
    cudaStreamWaitEvent(s1, evD, 0);

    // legacy: adj (DRAM-bound).  s1: wh + sreduce (FMA-bound), overlapped.
    k_adj<<<dim3(V_, B_), 256>>>(adj);
    cudaEventRecord(evA, 0);

    k_wh<<<dim3(16, G_, B_), 256, 0, s1>>>(h, W);
    k_sreduce<<<64, 64, 0, s1>>>();
    cudaEventRecord(evS, s1);

    // s1 chain: featin (needs zcol) -> re-zero zcol -> conv1 (cols 0..59)
    cudaStreamWaitEvent(s1, evA, 0);
    k_featin<<<dim3(V_, B_), 512, 0, s1>>>();
    k_zero<<<8, 1024, 0, s1>>>();
    k_conv<<<dim3(V_ / 16, B_), 512, 0, s1>>>(conv1_w, conv1_b, out, 0);

    // legacy chain: featout (needs S + rowmask) -> conv2 (cols 60..119)
    cudaStreamWaitEvent(0, evS, 0);
    k_featout<<<dim3(V_, B_), 512>>>();
    k_conv<<<dim3(V_ / 16, B_), 512>>>(conv2_w, conv2_b, out, 1);

    // join s1 back into legacy
    cudaEventRecord(evD, s1);
    cudaStreamWaitEvent(0, evD, 0);
}

// round 12
// speedup vs baseline: 1.2229x; 1.0933x over previous
#include <cuda_runtime.h>

#define ALPHA 0.2f
#define B_   8
#define G_   8
#define V_   1024
#define FOUT_ 64
#define C_   512
#define OUTW_ 60
#define OUTC_ 120

typedef unsigned long long ull;

// ---------------- scratch ----------------
__device__ __align__(16) float    g_Wh[B_*V_*C_];
__device__ __align__(16) float    g_Spart[B_*16*C_];
__device__ __align__(16) float    g_S[B_*C_];
__device__ unsigned               g_rowmask[B_*V_*32];
__device__ int                    g_zcol[B_*V_];        // zeroed at load; re-zeroed each replay after use
__device__ __align__(16) float    g_featin[B_*G_*V_*FOUT_];
__device__ __align__(16) float    g_featout[B_*G_*V_*FOUT_];

__device__ __forceinline__ float lrelu(float x) { return x >= 0.f ? x : ALPHA * x; }

__device__ __forceinline__ ull pack2(float x, float y) {
    ull r; asm("mov.b64 %0, {%1, %2};" : "=l"(r) : "f"(x), "f"(y)); return r;
}
__device__ __forceinline__ ull bcast2(float x) {
    ull r; asm("mov.b64 %0, {%1, %1};" : "=l"(r) : "f"(x)); return r;
}
__device__ __forceinline__ ull fma2(ull a, ull b, ull c) {
    ull d; asm("fma.rn.f32x2 %0, %1, %2, %3;" : "=l"(d) : "l"(a), "l"(b), "l"(c)); return d;
}
__device__ __forceinline__ float2 unpack2(ull v) {
    float2 r; asm("mov.b64 {%0, %1}, %2;" : "=f"(r.x), "=f"(r.y) : "l"(v)); return r;
}

__global__ void k_zero() {
    int t = blockIdx.x * blockDim.x + threadIdx.x;
    if (t < B_ * V_) g_zcol[t] = 0;
}

// ---------------- adj scan ----------------
__global__ void __launch_bounds__(256) k_adj(const int* __restrict__ adj) {
    int i = blockIdx.x, b = blockIdx.y;
    __shared__ unsigned mask[32];
    int t = threadIdx.x;
    if (t < 32) mask[t] = 0u;
    __syncthreads();
    const int4* p = (const int4*)(adj + (size_t)b * G_ * V_ * V_ + (size_t)i * V_);
    int4 acc = p[t];
#pragma unroll
    for (int g = 1; g < G_; g++) {
        int4 v = p[(size_t)g * (V_ * (V_ / 4)) + t];
        acc.x |= v.x; acc.y |= v.y; acc.z |= v.z; acc.w |= v.w;
    }
    unsigned nib = (unsigned)(acc.x == 0) | ((unsigned)(acc.y == 0) << 1) |
                   ((unsigned)(acc.z == 0) << 2) | ((unsigned)(acc.w == 0) << 3);
    if (nib) {
        atomicOr(&mask[t >> 3], nib << ((t & 7) * 4));
        int jb = b * V_ + 4 * t;
        if (acc.x == 0) atomicAdd(&g_zcol[jb + 0], 1);
        if (acc.y == 0) atomicAdd(&g_zcol[jb + 1], 1);
        if (acc.z == 0) atomicAdd(&g_zcol[jb + 2], 1);
        if (acc.w == 0) atomicAdd(&g_zcol[jb + 3], 1);
    }
    __syncthreads();
    if (t < 32) g_rowmask[((size_t)b * V_ + i) * 32 + t] = mask[t];
}

// ---------------- Wh GEMM ----------------
__global__ void __launch_bounds__(256) k_wh(const float* __restrict__ h,
                                            const float* __restrict__ W) {
    __shared__ __align__(16) float sW[64 * 64];
    __shared__ __align__(16) float sH[64 * 64];
    __shared__ float red[64 * 17];
    int t = threadIdx.x;
    int vt = blockIdx.x, g = blockIdx.y, b = blockIdx.z;
    const float4* wp = (const float4*)(W + (size_t)g * 4096);
    const float4* hp = (const float4*)(h + (((size_t)b * G_ + g) * V_ + (size_t)vt * 64) * 64);
    float4* sw4 = (float4*)sW;
    float4* sh4 = (float4*)sH;
#pragma unroll
    for (int q = t; q < 1024; q += 256) { sw4[q] = wp[q]; sh4[q] = hp[q]; }
    __syncthreads();
    int tx = t & 15, ty = t >> 4;
    int o0 = tx * 4, r0 = ty * 4;
    float acc[4][4] = {};
#pragma unroll 4
    for (int i = 0; i < 64; i++) {
        float4 bb = *(const float4*)(sW + i * 64 + o0);
#pragma unroll
        for (int r = 0; r < 4; r++) {
            float a = sH[(r0 + r) * 64 + i];
            acc[r][0] += a * bb.x; acc[r][1] += a * bb.y;
            acc[r][2] += a * bb.z; acc[r][3] += a * bb.w;
        }
    }
    float cs[4] = {0.f, 0.f, 0.f, 0.f};
#pragma unroll
    for (int r = 0; r < 4; r++) {
        float4 v;
        v.x = lrelu(acc[r][0]); v.y = lrelu(acc[r][1]);
        v.z = lrelu(acc[r][2]); v.w = lrelu(acc[r][3]);
        size_t row = (size_t)b * V_ + vt * 64 + r0 + r;
        *(float4*)(g_Wh + row * C_ + g * 64 + o0) = v;
        cs[0] += v.x; cs[1] += v.y; cs[2] += v.z; cs[3] += v.w;
    }
    __syncthreads();
#pragma unroll
    for (int j = 0; j < 4; j++) red[(o0 + j) * 17 + ty] = cs[j];
    __syncthreads();
    if (t < 64) {
        float s = 0.f;
#pragma unroll
        for (int k = 0; k < 16; k++) s += red[t * 17 + k];
        g_Spart[((size_t)b * 16 + vt) * C_ + g * 64 + t] = s;
    }
}

__global__ void k_sreduce() {
    int b = blockIdx.x >> 3;
    int c = (blockIdx.x & 7) * 64 + threadIdx.x;
    float s = 0.f;
#pragma unroll
    for (int vt = 0; vt < 16; vt++) s += g_Spart[((size_t)b * 16 + vt) * C_ + c];
    g_S[b * C_ + c] = s;
}

// ---------------- merged feat: fin + fout, float4-vectorized ----------------
// grid (V, B), block 128. Thread t owns channels 4t..4t+3.
__global__ void __launch_bounds__(128) k_feat2() {
    int i = blockIdx.x, b = blockIdx.y;
    int t = threadIdx.x;
    __shared__ short jlist[64];
    __shared__ int njs;
    __shared__ float sdeg;

    if (t == 0) sdeg = (float)(V_ - g_zcol[b * V_ + i]) * (1.0f / V_);
    if (t < 32) {
        unsigned mw = g_rowmask[((size_t)b * V_ + i) * 32 + t];
        int cnt = __popc(mw);
        int pre = cnt;
#pragma unroll
        for (int d = 1; d < 32; d <<= 1) {
            int v = __shfl_up_sync(0xffffffffu, pre, d);
            if (t >= d) pre += v;
        }
        int excl = pre - cnt;
        if (t == 31) njs = pre;
        while (mw) {
            int p = __ffs(mw) - 1;
            mw &= mw - 1;
            jlist[excl++] = (short)(t * 32 + p);
        }
    }
    __syncthreads();

    const float4* whb = (const float4*)(g_Wh + (size_t)b * V_ * C_) + t;  // row stride 128
    float4 S = ((const float4*)(g_S + b * C_))[t];
    float cx = 0.f, cy = 0.f, cz = 0.f, cw = 0.f;
    int n = njs;
#pragma unroll 1
    for (int k = 0; k < n; k += 2) {
        float4 v0 = whb[(size_t)jlist[k] * 128];
        float4 v1 = (k + 1 < n) ? whb[(size_t)jlist[k + 1] * 128]
                                : make_float4(0.f, 0.f, 0.f, 0.f);
        cx += v0.x + v1.x; cy += v0.y + v1.y;
        cz += v0.z + v1.z; cw += v0.w + v1.w;
    }
    float4 wv = whb[(size_t)i * 128];
    float deg = sdeg;

    float4 fin, fout;
    fin.x  = lrelu(deg * wv.x);             fin.y  = lrelu(deg * wv.y);
    fin.z  = lrelu(deg * wv.z);             fin.w  = lrelu(deg * wv.w);
    fout.x = lrelu((S.x - cx) * (1.0f / V_)); fout.y = lrelu((S.y - cy) * (1.0f / V_));
    fout.z = lrelu((S.z - cz) * (1.0f / V_)); fout.w = lrelu((S.w - cw) * (1.0f / V_));

    int g = t >> 4, o4 = t & 15;
    size_t oidx = (((size_t)b * G_ + g) * V_ + i) * FOUT_ + o4 * 4;
    *(float4*)(g_featin + oidx)  = fin;
    *(float4*)(g_featout + oidx) = fout;
}

// ---------------- conv (R2-proven direct); which selects plane/cols ----------
__global__ void __launch_bounds__(512) k_conv(const float* __restrict__ cw,
                                              const float* __restrict__ cb,
                                              float* __restrict__ out,
                                              int which) {
    int b = blockIdx.y;
    int r0 = blockIdx.x * 16;
    int coloff = which ? OUTW_ : 0;

    __shared__ __align__(16) float sin_[8][20][64];
    __shared__ __align__(8) float2 swt2[4 * 8 * 25];
    __shared__ float2 sb2[4];

    const float* feat = which ? g_featout : g_featin;

    int t = threadIdx.x;
    for (int q = t; q < 800; q += 512) {
        int gg = q / 200;
        int rem = q - gg * 200;
        swt2[q] = make_float2(cw[(2 * gg) * 200 + rem], cw[(2 * gg + 1) * 200 + rem]);
    }
    if (t < 4) sb2[t] = make_float2(cb[2 * t], cb[2 * t + 1]);

#pragma unroll
    for (int q = t; q < 2560; q += 512) {
        int cin = q / 320;
        int rem = q - cin * 320;
        int row = rem >> 4;
        int o4  = rem & 15;
        int v = r0 - 2 + row;
        float4 val = make_float4(0.f, 0.f, 0.f, 0.f);
        if (v >= 0 && v < V_)
            val = *(const float4*)(feat + (((size_t)b * G_ + cin) * V_ + v) * FOUT_ + o4 * 4);
        *(float4*)(&sin_[cin][row][o4 * 4]) = val;
    }
    __syncthreads();

    int cg = t & 15, rg = (t >> 4) & 7, gg = t >> 7;
    if (cg < 15) {
        int w0 = cg * 4;
        int lr = rg * 2;

        ull bias = pack2(sb2[gg].x, sb2[gg].y);
        ull acc[2][4];
#pragma unroll
        for (int r = 0; r < 2; r++)
#pragma unroll
            for (int c = 0; c < 4; c++) acc[r][c] = bias;

        const float2* wp = &swt2[gg * 200];

#pragma unroll 1
        for (int cin = 0; cin < 8; cin++) {
#pragma unroll
            for (int kh = 0; kh < 5; kh++) {
                ull in2[2][8];
#pragma unroll
                for (int rr = 0; rr < 2; rr++) {
                    float4 a4 = *(const float4*)(&sin_[cin][lr + kh + rr][w0]);
                    float4 b4 = *(const float4*)(&sin_[cin][lr + kh + rr][w0 + 4]);
                    in2[rr][0] = bcast2(a4.x); in2[rr][1] = bcast2(a4.y);
                    in2[rr][2] = bcast2(a4.z); in2[rr][3] = bcast2(a4.w);
                    in2[rr][4] = bcast2(b4.x); in2[rr][5] = bcast2(b4.y);
                    in2[rr][6] = bcast2(b4.z); in2[rr][7] = bcast2(b4.w);
                }
#pragma unroll
                for (int kw = 0; kw < 5; kw++) {
                    float2 w2 = wp[cin * 25 + kh * 5 + kw];
                    ull wt = pack2(w2.x, w2.y);
#pragma unroll
                    for (int r = 0; r < 2; r++) {
#pragma unroll
                        for (int c = 0; c < 4; c++)
                            acc[r][c] = fma2(in2[r][kw + c], wt, acc[r][c]);
                    }
                }
            }
        }

#pragma unroll
        for (int r = 0; r < 2; r++) {
            float2 u0 = unpack2(acc[r][0]);
            float2 u1 = unpack2(acc[r][1]);
            float2 u2 = unpack2(acc[r][2]);
            float2 u3 = unpack2(acc[r][3]);
            int v = r0 + lr + r;
            size_t base0 = (((size_t)b * G_ + (2 * gg)) * V_ + v) * OUTC_ + coloff + w0;
            size_t base1 = (((size_t)b * G_ + (2 * gg + 1)) * V_ + v) * OUTC_ + coloff + w0;
            *(float4*)(out + base0) = make_float4(u0.x, u1.x, u2.x, u3.x);
            *(float4*)(out + base1) = make_float4(u0.y, u1.y, u2.y, u3.y);
        }
    }
}

// ---------------- launch ----------------
extern "C" void kernel_launch(void* const* d_in, const int* in_sizes, int n_in,
                              void* d_out, int out_size) {
    const float* h       = (const float*)d_in[0];
    const int*   adj     = (const int*)d_in[1];
    const float* W       = (const float*)d_in[2];
    const float* conv1_w = (const float*)d_in[3];
    const float* conv1_b = (const float*)d_in[4];
    const float* conv2_w = (const float*)d_in[5];
    const float* conv2_b = (const float*)d_in[6];
    float* out = (float*)d_out;

    static cudaStream_t s1 = nullptr;
    static cudaEvent_t evS = nullptr, evF = nullptr, evD = nullptr;
    if (s1 == nullptr) {
        cudaStreamCreateWithFlags(&s1, cudaStreamNonBlocking);
        cudaEventCreateWithFlags(&evS, cudaEventDisableTiming);
        cudaEventCreateWithFlags(&evF, cudaEventDisableTiming);
        cudaEventCreateWithFlags(&evD, cudaEventDisableTiming);
    }

    // fork s1 from legacy
    cudaEventRecord(evD, 0);
    cudaStreamWaitEvent(s1, evD, 0);

    // legacy: adj (DRAM-bound)  ∥  s1: wh + sreduce (FMA-bound)
    k_adj<<<dim3(V_, B_), 256>>>(adj);
    k_wh<<<dim3(16, G_, B_), 256, 0, s1>>>(h, W);
    k_sreduce<<<64, 64, 0, s1>>>();
    cudaEventRecord(evS, s1);

    // merged feat on legacy (needs adj outputs + S)
    cudaStreamWaitEvent(0, evS, 0);
    k_feat2<<<dim3(V_, B_), 128>>>();
    cudaEventRecord(evF, 0);

    // s1: re-zero zcol (last consumer was feat2) + conv1; legacy: conv2
    cudaStreamWaitEvent(s1, evF, 0);
    k_zero<<<8, 1024, 0, s1>>>();
    k_conv<<<dim3(V_ / 16, B_), 512, 0, s1>>>(conv1_w, conv1_b, out, 0);
    k_conv<<<dim3(V_ / 16, B_), 512>>>(conv2_w, conv2_b, out, 1);

    // join
    cudaEventRecord(evD, s1);
    cudaStreamWaitEvent(0, evD, 0);
}

// round 13
// speedup vs baseline: 1.2559x; 1.0270x over previous
#include <cuda_runtime.h>

#define ALPHA 0.2f
#define B_   8
#define G_   8
#define V_   1024
#define FOUT_ 64
#define C_   512
#define OUTW_ 60
#define OUTC_ 120

typedef unsigned long long ull;

// ---------------- scratch ----------------
__device__ __align__(16) float    g_Wh[B_*V_*C_];
__device__ __align__(16) float    g_Spart[B_*16*C_];
__device__ __align__(16) float    g_S[B_*C_];
__device__ unsigned               g_rowmask[B_*V_*32];
__device__ int                    g_zcol[B_*V_];        // zeroed at load; re-zeroed each replay after last use
__device__ __align__(16) float    g_featout[B_*G_*V_*FOUT_];

__device__ __forceinline__ float lrelu(float x) { return x >= 0.f ? x : ALPHA * x; }

__device__ __forceinline__ ull pack2(float x, float y) {
    ull r; asm("mov.b64 %0, {%1, %2};" : "=l"(r) : "f"(x), "f"(y)); return r;
}
__device__ __forceinline__ ull bcast2(float x) {
    ull r; asm("mov.b64 %0, {%1, %1};" : "=l"(r) : "f"(x)); return r;
}
__device__ __forceinline__ ull fma2(ull a, ull b, ull c) {
    ull d; asm("fma.rn.f32x2 %0, %1, %2, %3;" : "=l"(d) : "l"(a), "l"(b), "l"(c)); return d;
}
__device__ __forceinline__ float2 unpack2(ull v) {
    float2 r; asm("mov.b64 {%0, %1}, %2;" : "=f"(r.x), "=f"(r.y) : "l"(v)); return r;
}

__global__ void k_zero() {
    int t = blockIdx.x * blockDim.x + threadIdx.x;
    if (t < B_ * V_) g_zcol[t] = 0;
}

// ---------------- adj scan ----------------
__global__ void __launch_bounds__(256) k_adj(const int* __restrict__ adj) {
    int i = blockIdx.x, b = blockIdx.y;
    __shared__ unsigned mask[32];
    int t = threadIdx.x;
    if (t < 32) mask[t] = 0u;
    __syncthreads();
    const int4* p = (const int4*)(adj + (size_t)b * G_ * V_ * V_ + (size_t)i * V_);
    int4 acc = p[t];
#pragma unroll
    for (int g = 1; g < G_; g++) {
        int4 v = p[(size_t)g * (V_ * (V_ / 4)) + t];
        acc.x |= v.x; acc.y |= v.y; acc.z |= v.z; acc.w |= v.w;
    }
    unsigned nib = (unsigned)(acc.x == 0) | ((unsigned)(acc.y == 0) << 1) |
                   ((unsigned)(acc.z == 0) << 2) | ((unsigned)(acc.w == 0) << 3);
    if (nib) {
        atomicOr(&mask[t >> 3], nib << ((t & 7) * 4));
        int jb = b * V_ + 4 * t;
        if (acc.x == 0) atomicAdd(&g_zcol[jb + 0], 1);
        if (acc.y == 0) atomicAdd(&g_zcol[jb + 1], 1);
        if (acc.z == 0) atomicAdd(&g_zcol[jb + 2], 1);
        if (acc.w == 0) atomicAdd(&g_zcol[jb + 3], 1);
    }
    __syncthreads();
    if (t < 32) g_rowmask[((size_t)b * V_ + i) * 32 + t] = mask[t];
}

// ---------------- Wh GEMM ----------------
__global__ void __launch_bounds__(256) k_wh(const float* __restrict__ h,
                                            const float* __restrict__ W) {
    __shared__ __align__(16) float sW[64 * 64];
    __shared__ __align__(16) float sH[64 * 64];
    __shared__ float red[64 * 17];
    int t = threadIdx.x;
    int vt = blockIdx.x, g = blockIdx.y, b = blockIdx.z;
    const float4* wp = (const float4*)(W + (size_t)g * 4096);
    const float4* hp = (const float4*)(h + (((size_t)b * G_ + g) * V_ + (size_t)vt * 64) * 64);
    float4* sw4 = (float4*)sW;
    float4* sh4 = (float4*)sH;
#pragma unroll
    for (int q = t; q < 1024; q += 256) { sw4[q] = wp[q]; sh4[q] = hp[q]; }
    __syncthreads();
    int tx = t & 15, ty = t >> 4;
    int o0 = tx * 4, r0 = ty * 4;
    float acc[4][4] = {};
#pragma unroll 4
    for (int i = 0; i < 64; i++) {
        float4 bb = *(const float4*)(sW + i * 64 + o0);
#pragma unroll
        for (int r = 0; r < 4; r++) {
            float a = sH[(r0 + r) * 64 + i];
            acc[r][0] += a * bb.x; acc[r][1] += a * bb.y;
            acc[r][2] += a * bb.z; acc[r][3] += a * bb.w;
        }
    }
    float cs[4] = {0.f, 0.f, 0.f, 0.f};
#pragma unroll
    for (int r = 0; r < 4; r++) {
        float4 v;
        v.x = lrelu(acc[r][0]); v.y = lrelu(acc[r][1]);
        v.z = lrelu(acc[r][2]); v.w = lrelu(acc[r][3]);
        size_t row = (size_t)b * V_ + vt * 64 + r0 + r;
        *(float4*)(g_Wh + row * C_ + g * 64 + o0) = v;
        cs[0] += v.x; cs[1] += v.y; cs[2] += v.z; cs[3] += v.w;
    }
    __syncthreads();
#pragma unroll
    for (int j = 0; j < 4; j++) red[(o0 + j) * 17 + ty] = cs[j];
    __syncthreads();
    if (t < 64) {
        float s = 0.f;
#pragma unroll
        for (int k = 0; k < 16; k++) s += red[t * 17 + k];
        g_Spart[((size_t)b * 16 + vt) * C_ + g * 64 + t] = s;
    }
}

__global__ void k_sreduce() {
    int b = blockIdx.x >> 3;
    int c = (blockIdx.x & 7) * 64 + threadIdx.x;
    float s = 0.f;
#pragma unroll
    for (int vt = 0; vt < 16; vt++) s += g_Spart[((size_t)b * 16 + vt) * C_ + c];
    g_S[b * C_ + c] = s;
}

// ---------------- featout only: fout = lrelu((S - corr)/V), float4 ----------
__global__ void __launch_bounds__(128) k_featout() {
    int i = blockIdx.x, b = blockIdx.y;
    int t = threadIdx.x;
    __shared__ short jlist[64];
    __shared__ int njs;

    if (t < 32) {
        unsigned mw = g_rowmask[((size_t)b * V_ + i) * 32 + t];
        int cnt = __popc(mw);
        int pre = cnt;
#pragma unroll
        for (int d = 1; d < 32; d <<= 1) {
            int v = __shfl_up_sync(0xffffffffu, pre, d);
            if (t >= d) pre += v;
        }
        int excl = pre - cnt;
        if (t == 31) njs = pre;
        while (mw) {
            int p = __ffs(mw) - 1;
            mw &= mw - 1;
            jlist[excl++] = (short)(t * 32 + p);
        }
    }
    __syncthreads();

    const float4* whb = (const float4*)(g_Wh + (size_t)b * V_ * C_) + t;  // row stride 128
    float4 S = ((const float4*)(g_S + b * C_))[t];
    float cx = 0.f, cy = 0.f, cz = 0.f, cw = 0.f;
    int n = njs;
#pragma unroll 1
    for (int k = 0; k < n; k += 2) {
        float4 v0 = whb[(size_t)jlist[k] * 128];
        float4 v1 = (k + 1 < n) ? whb[(size_t)jlist[k + 1] * 128]
                                : make_float4(0.f, 0.f, 0.f, 0.f);
        cx += v0.x + v1.x; cy += v0.y + v1.y;
        cz += v0.z + v1.z; cw += v0.w + v1.w;
    }
    float4 fout;
    fout.x = lrelu((S.x - cx) * (1.0f / V_)); fout.y = lrelu((S.y - cy) * (1.0f / V_));
    fout.z = lrelu((S.z - cz) * (1.0f / V_)); fout.w = lrelu((S.w - cw) * (1.0f / V_));

    int g = t >> 4, o4 = t & 15;
    *(float4*)(g_featout + (((size_t)b * G_ + g) * V_ + i) * FOUT_ + o4 * 4) = fout;
}

// ---------------- conv; which=0 reads Wh*deg inline (featin fused) -----------
__global__ void __launch_bounds__(512) k_conv(const float* __restrict__ cw,
                                              const float* __restrict__ cb,
                                              float* __restrict__ out,
                                              int which) {
    int b = blockIdx.y;
    int r0 = blockIdx.x * 16;
    int coloff = which ? OUTW_ : 0;

    __shared__ __align__(16) float sin_[8][20][64];
    __shared__ __align__(8) float2 swt2[4 * 8 * 25];
    __shared__ float2 sb2[4];
    __shared__ float sdeg[20];

    int t = threadIdx.x;
    if (which == 0 && t < 20) {
        int v = r0 - 2 + t;
        sdeg[t] = (v >= 0 && v < V_)
                ? (float)(V_ - g_zcol[b * V_ + v]) * (1.0f / V_) : 0.f;
    }
    for (int q = t; q < 800; q += 512) {
        int gg = q / 200;
        int rem = q - gg * 200;
        swt2[q] = make_float2(cw[(2 * gg) * 200 + rem], cw[(2 * gg + 1) * 200 + rem]);
    }
    if (t < 4) sb2[t] = make_float2(cb[2 * t], cb[2 * t + 1]);
    __syncthreads();

    if (which) {
#pragma unroll
        for (int q = t; q < 2560; q += 512) {
            int cin = q / 320;
            int rem = q - cin * 320;
            int row = rem >> 4;
            int o4  = rem & 15;
            int v = r0 - 2 + row;
            float4 val = make_float4(0.f, 0.f, 0.f, 0.f);
            if (v >= 0 && v < V_)
                val = *(const float4*)(g_featout + (((size_t)b * G_ + cin) * V_ + v) * FOUT_ + o4 * 4);
            *(float4*)(&sin_[cin][row][o4 * 4]) = val;
        }
    } else {
        // featin fused: lrelu(deg[v] * Wh[b,v, cin*64 + o]) staged directly
#pragma unroll
        for (int q = t; q < 2560; q += 512) {
            int cin = q / 320;
            int rem = q - cin * 320;
            int row = rem >> 4;
            int o4  = rem & 15;
            int v = r0 - 2 + row;
            float4 val = make_float4(0.f, 0.f, 0.f, 0.f);
            if (v >= 0 && v < V_) {
                float4 wv = *(const float4*)(g_Wh + ((size_t)b * V_ + v) * C_ + cin * 64 + o4 * 4);
                float d = sdeg[row];
                val.x = lrelu(d * wv.x); val.y = lrelu(d * wv.y);
                val.z = lrelu(d * wv.z); val.w = lrelu(d * wv.w);
            }
            *(float4*)(&sin_[cin][row][o4 * 4]) = val;
        }
    }
    __syncthreads();

    int cg = t & 15, rg = (t >> 4) & 7, gg = t >> 7;
    if (cg < 15) {
        int w0 = cg * 4;
        int lr = rg * 2;

        ull bias = pack2(sb2[gg].x, sb2[gg].y);
        ull acc[2][4];
#pragma unroll
        for (int r = 0; r < 2; r++)
#pragma unroll
            for (int c = 0; c < 4; c++) acc[r][c] = bias;

        const float2* wp = &swt2[gg * 200];

#pragma unroll 1
        for (int cin = 0; cin < 8; cin++) {
#pragma unroll
            for (int kh = 0; kh < 5; kh++) {
                ull in2[2][8];
#pragma unroll
                for (int rr = 0; rr < 2; rr++) {
                    float4 a4 = *(const float4*)(&sin_[cin][lr + kh + rr][w0]);
                    float4 b4 = *(const float4*)(&sin_[cin][lr + kh + rr][w0 + 4]);
                    in2[rr][0] = bcast2(a4.x); in2[rr][1] = bcast2(a4.y);
                    in2[rr][2] = bcast2(a4.z); in2[rr][3] = bcast2(a4.w);
                    in2[rr][4] = bcast2(b4.x); in2[rr][5] = bcast2(b4.y);
                    in2[rr][6] = bcast2(b4.z); in2[rr][7] = bcast2(b4.w);
                }
#pragma unroll
                for (int kw = 0; kw < 5; kw++) {
                    float2 w2 = wp[cin * 25 + kh * 5 + kw];
                    ull wt = pack2(w2.x, w2.y);
#pragma unroll
                    for (int r = 0; r < 2; r++) {
#pragma unroll
                        for (int c = 0; c < 4; c++)
                            acc[r][c] = fma2(in2[r][kw + c], wt, acc[r][c]);
                    }
                }
            }
        }

#pragma unroll
        for (int r = 0; r < 2; r++) {
            float2 u0 = unpack2(acc[r][0]);
            float2 u1 = unpack2(acc[r][1]);
            float2 u2 = unpack2(acc[r][2]);
            float2 u3 = unpack2(acc[r][3]);
            int v = r0 + lr + r;
            size_t base0 = (((size_t)b * G_ + (2 * gg)) * V_ + v) * OUTC_ + coloff + w0;
            size_t base1 = (((size_t)b * G_ + (2 * gg + 1)) * V_ + v) * OUTC_ + coloff + w0;
            *(float4*)(out + base0) = make_float4(u0.x, u1.x, u2.x, u3.x);
            *(float4*)(out + base1) = make_float4(u0.y, u1.y, u2.y, u3.y);
        }
    }
}

// ---------------- launch ----------------
extern "C" void kernel_launch(void* const* d_in, const int* in_sizes, int n_in,
                              void* d_out, int out_size) {
    const float* h       = (const float*)d_in[0];
    const int*   adj     = (const int*)d_in[1];
    const float* W       = (const float*)d_in[2];
    const float* conv1_w = (const float*)d_in[3];
    const float* conv1_b = (const float*)d_in[4];
    const float* conv2_w = (const float*)d_in[5];
    const float* conv2_b = (const float*)d_in[6];
    float* out = (float*)d_out;

    static cudaStream_t s1 = nullptr;
    static cudaEvent_t evA = nullptr, evW = nullptr, evD = nullptr;
    if (s1 == nullptr) {
        cudaStreamCreateWithFlags(&s1, cudaStreamNonBlocking);
        cudaEventCreateWithFlags(&evA, cudaEventDisableTiming);
        cudaEventCreateWithFlags(&evW, cudaEventDisableTiming);
        cudaEventCreateWithFlags(&evD, cudaEventDisableTiming);
    }

    // fork s1 from legacy
    cudaEventRecord(evD, 0);
    cudaStreamWaitEvent(s1, evD, 0);

    // legacy: adj (DRAM-bound)  ∥  s1: wh + sreduce (FMA-bound)
    k_adj<<<dim3(V_, B_), 256>>>(adj);
    cudaEventRecord(evA, 0);

    k_wh<<<dim3(16, G_, B_), 256, 0, s1>>>(h, W);
    cudaEventRecord(evW, s1);
    k_sreduce<<<64, 64, 0, s1>>>();

    // legacy: conv1 (featin fused; needs Wh + zcol) -> re-zero zcol
    cudaStreamWaitEvent(0, evW, 0);
    k_conv<<<dim3(V_ / 16, B_), 512>>>(conv1_w, conv1_b, out, 0);
    k_zero<<<8, 1024>>>();

    // s1: featout (needs rowmask + S) -> conv2; overlaps conv1
    cudaStreamWaitEvent(s1, evA, 0);
    k_featout<<<dim3(V_, B_), 128, 0, s1>>>();
    k_conv<<<dim3(V_ / 16, B_), 512, 0, s1>>>(conv2_w, conv2_b, out, 1);

    // join
    cudaEventRecord(evD, s1);
    cudaStreamWaitEvent(0, evD, 0);
}

// round 15
// speedup vs baseline: 1.2739x; 1.0143x over previous
#include <cuda_runtime.h>

#define ALPHA 0.2f
#define B_   8
#define G_   8
#define V_   1024
#define FOUT_ 64
#define C_   512
#define OUTW_ 60
#define OUTC_ 120

typedef unsigned long long ull;

// ---------------- scratch ----------------
__device__ __align__(16) float    g_Wh[B_*V_*C_];
__device__ __align__(16) float    g_Spart[B_*16*C_];
__device__ __align__(16) float    g_S[B_*C_];
__device__ unsigned               g_rowmask[B_*V_*32];
__device__ int                    g_zcol[B_*V_];        // zeroed at load; re-zeroed each replay after last use
__device__ __align__(16) float    g_featout[B_*G_*V_*FOUT_];

__device__ __forceinline__ float lrelu(float x) { return x >= 0.f ? x : ALPHA * x; }

__device__ __forceinline__ ull pack2(float x, float y) {
    ull r; asm("mov.b64 %0, {%1, %2};" : "=l"(r) : "f"(x), "f"(y)); return r;
}
__device__ __forceinline__ ull bcast2(float x) {
    ull r; asm("mov.b64 %0, {%1, %1};" : "=l"(r) : "f"(x)); return r;
}
__device__ __forceinline__ ull fma2(ull a, ull b, ull c) {
    ull d; asm("fma.rn.f32x2 %0, %1, %2, %3;" : "=l"(d) : "l"(a), "l"(b), "l"(c)); return d;
}
__device__ __forceinline__ float2 unpack2(ull v) {
    float2 r; asm("mov.b64 {%0, %1}, %2;" : "=f"(r.x), "=f"(r.y) : "l"(v)); return r;
}

__global__ void k_zero() {
    int t = blockIdx.x * blockDim.x + threadIdx.x;
    if (t < B_ * V_) g_zcol[t] = 0;
}

// ---------------- adj scan, 4 batches per launch (b = b0 + blockIdx.y) -------
__global__ void __launch_bounds__(256) k_adj(const int* __restrict__ adj, int b0) {
    int i = blockIdx.x, b = b0 + blockIdx.y;
    __shared__ unsigned mask[32];
    int t = threadIdx.x;
    if (t < 32) mask[t] = 0u;
    __syncthreads();
    const int4* p = (const int4*)(adj + (size_t)b * G_ * V_ * V_ + (size_t)i * V_);
    int4 acc = p[t];
#pragma unroll
    for (int g = 1; g < G_; g++) {
        int4 v = p[(size_t)g * (V_ * (V_ / 4)) + t];
        acc.x |= v.x; acc.y |= v.y; acc.z |= v.z; acc.w |= v.w;
    }
    unsigned nib = (unsigned)(acc.x == 0) | ((unsigned)(acc.y == 0) << 1) |
                   ((unsigned)(acc.z == 0) << 2) | ((unsigned)(acc.w == 0) << 3);
    if (nib) {
        atomicOr(&mask[t >> 3], nib << ((t & 7) * 4));
        int jb = b * V_ + 4 * t;
        if (acc.x == 0) atomicAdd(&g_zcol[jb + 0], 1);
        if (acc.y == 0) atomicAdd(&g_zcol[jb + 1], 1);
        if (acc.z == 0) atomicAdd(&g_zcol[jb + 2], 1);
        if (acc.w == 0) atomicAdd(&g_zcol[jb + 3], 1);
    }
    __syncthreads();
    if (t < 32) g_rowmask[((size_t)b * V_ + i) * 32 + t] = mask[t];
}

// ---------------- Wh GEMM ----------------
__global__ void __launch_bounds__(256) k_wh(const float* __restrict__ h,
                                            const float* __restrict__ W) {
    __shared__ __align__(16) float sW[64 * 64];
    __shared__ __align__(16) float sH[64 * 64];
    __shared__ float red[64 * 17];
    int t = threadIdx.x;
    int vt = blockIdx.x, g = blockIdx.y, b = blockIdx.z;
    const float4* wp = (const float4*)(W + (size_t)g * 4096);
    const float4* hp = (const float4*)(h + (((size_t)b * G_ + g) * V_ + (size_t)vt * 64) * 64);
    float4* sw4 = (float4*)sW;
    float4* sh4 = (float4*)sH;
#pragma unroll
    for (int q = t; q < 1024; q += 256) { sw4[q] = wp[q]; sh4[q] = hp[q]; }
    __syncthreads();
    int tx = t & 15, ty = t >> 4;
    int o0 = tx * 4, r0 = ty * 4;
    float acc[4][4] = {};
#pragma unroll 4
    for (int i = 0; i < 64; i++) {
        float4 bb = *(const float4*)(sW + i * 64 + o0);
#pragma unroll
        for (int r = 0; r < 4; r++) {
            float a = sH[(r0 + r) * 64 + i];
            acc[r][0] += a * bb.x; acc[r][1] += a * bb.y;
            acc[r][2] += a * bb.z; acc[r][3] += a * bb.w;
        }
    }
    float cs[4] = {0.f, 0.f, 0.f, 0.f};
#pragma unroll
    for (int r = 0; r < 4; r++) {
        float4 v;
        v.x = lrelu(acc[r][0]); v.y = lrelu(acc[r][1]);
        v.z = lrelu(acc[r][2]); v.w = lrelu(acc[r][3]);
        size_t row = (size_t)b * V_ + vt * 64 + r0 + r;
        *(float4*)(g_Wh + row * C_ + g * 64 + o0) = v;
        cs[0] += v.x; cs[1] += v.y; cs[2] += v.z; cs[3] += v.w;
    }
    __syncthreads();
#pragma unroll
    for (int j = 0; j < 4; j++) red[(o0 + j) * 17 + ty] = cs[j];
    __syncthreads();
    if (t < 64) {
        float s = 0.f;
#pragma unroll
        for (int k = 0; k < 16; k++) s += red[t * 17 + k];
        g_Spart[((size_t)b * 16 + vt) * C_ + g * 64 + t] = s;
    }
}

__global__ void k_sreduce() {
    int b = blockIdx.x >> 3;
    int c = (blockIdx.x & 7) * 64 + threadIdx.x;
    float s = 0.f;
#pragma unroll
    for (int vt = 0; vt < 16; vt++) s += g_Spart[((size_t)b * 16 + vt) * C_ + c];
    g_S[b * C_ + c] = s;
}

// ---------------- featout, 4 batches per launch ----------------
__global__ void __launch_bounds__(128) k_featout(int b0) {
    int i = blockIdx.x, b = b0 + blockIdx.y;
    int t = threadIdx.x;
    __shared__ short jlist[64];
    __shared__ int njs;

    if (t < 32) {
        unsigned mw = g_rowmask[((size_t)b * V_ + i) * 32 + t];
        int cnt = __popc(mw);
        int pre = cnt;
#pragma unroll
        for (int d = 1; d < 32; d <<= 1) {
            int v = __shfl_up_sync(0xffffffffu, pre, d);
            if (t >= d) pre += v;
        }
        int excl = pre - cnt;
        if (t == 31) njs = pre;
        while (mw) {
            int p = __ffs(mw) - 1;
            mw &= mw - 1;
            jlist[excl++] = (short)(t * 32 + p);
        }
    }
    __syncthreads();

    const float4* whb = (const float4*)(g_Wh + (size_t)b * V_ * C_) + t;
    float4 S = ((const float4*)(g_S + b * C_))[t];
    float cx = 0.f, cy = 0.f, cz = 0.f, cw = 0.f;
    int n = njs;
#pragma unroll 1
    for (int k = 0; k < n; k += 2) {
        float4 v0 = whb[(size_t)jlist[k] * 128];
        float4 v1 = (k + 1 < n) ? whb[(size_t)jlist[k + 1] * 128]
                                : make_float4(0.f, 0.f, 0.f, 0.f);
        cx += v0.x + v1.x; cy += v0.y + v1.y;
        cz += v0.z + v1.z; cw += v0.w + v1.w;
    }
    float4 fout;
    fout.x = lrelu((S.x - cx) * (1.0f / V_)); fout.y = lrelu((S.y - cy) * (1.0f / V_));
    fout.z = lrelu((S.z - cz) * (1.0f / V_)); fout.w = lrelu((S.w - cw) * (1.0f / V_));

    int g = t >> 4, o4 = t & 15;
    *(float4*)(g_featout + (((size_t)b * G_ + g) * V_ + i) * FOUT_ + o4 * 4) = fout;
}

// ---------------- conv, 4 batches per launch; which=0 fuses featin -----------
__global__ void __launch_bounds__(512) k_conv(const float* __restrict__ cw,
                                              const float* __restrict__ cb,
                                              float* __restrict__ out,
                                              int which, int b0) {
    int b = b0 + blockIdx.y;
    int r0 = blockIdx.x * 16;
    int coloff = which ? OUTW_ : 0;

    __shared__ __align__(16) float sin_[8][20][64];
    __shared__ __align__(8) float2 swt2[4 * 8 * 25];
    __shared__ float2 sb2[4];
    __shared__ float sdeg[20];

    int t = threadIdx.x;
    if (which == 0 && t < 20) {
        int v = r0 - 2 + t;
        sdeg[t] = (v >= 0 && v < V_)
                ? (float)(V_ - g_zcol[b * V_ + v]) * (1.0f / V_) : 0.f;
    }
    for (int q = t; q < 800; q += 512) {
        int gg = q / 200;
        int rem = q - gg * 200;
        swt2[q] = make_float2(cw[(2 * gg) * 200 + rem], cw[(2 * gg + 1) * 200 + rem]);
    }
    if (t < 4) sb2[t] = make_float2(cb[2 * t], cb[2 * t + 1]);
    __syncthreads();

    if (which) {
#pragma unroll
        for (int q = t; q < 2560; q += 512) {
            int cin = q / 320;
            int rem = q - cin * 320;
            int row = rem >> 4;
            int o4  = rem & 15;
            int v = r0 - 2 + row;
            float4 val = make_float4(0.f, 0.f, 0.f, 0.f);
            if (v >= 0 && v < V_)
                val = *(const float4*)(g_featout + (((size_t)b * G_ + cin) * V_ + v) * FOUT_ + o4 * 4);
            *(float4*)(&sin_[cin][row][o4 * 4]) = val;
        }
    } else {
#pragma unroll
        for (int q = t; q < 2560; q += 512) {
            int cin = q / 320;
            int rem = q - cin * 320;
            int row = rem >> 4;
            int o4  = rem & 15;
            int v = r0 - 2 + row;
            float4 val = make_float4(0.f, 0.f, 0.f, 0.f);
            if (v >= 0 && v < V_) {
                float4 wv = *(const float4*)(g_Wh + ((size_t)b * V_ + v) * C_ + cin * 64 + o4 * 4);
                float d = sdeg[row];
                val.x = lrelu(d * wv.x); val.y = lrelu(d * wv.y);
                val.z = lrelu(d * wv.z); val.w = lrelu(d * wv.w);
            }
            *(float4*)(&sin_[cin][row][o4 * 4]) = val;
        }
    }
    __syncthreads();

    int cg = t & 15, rg = (t >> 4) & 7, gg = t >> 7;
    if (cg < 15) {
        int w0 = cg * 4;
        int lr = rg * 2;

        ull bias = pack2(sb2[gg].x, sb2[gg].y);
        ull acc[2][4];
#pragma unroll
        for (int r = 0; r < 2; r++)
#pragma unroll
            for (int c = 0; c < 4; c++) acc[r][c] = bias;

        const float2* wp = &swt2[gg * 200];

#pragma unroll 1
        for (int cin = 0; cin < 8; cin++) {
#pragma unroll
            for (int kh = 0; kh < 5; kh++) {
                ull in2[2][8];
#pragma unroll
                for (int rr = 0; rr < 2; rr++) {
                    float4 a4 = *(const float4*)(&sin_[cin][lr + kh + rr][w0]);
                    float4 b4 = *(const float4*)(&sin_[cin][lr + kh + rr][w0 + 4]);
                    in2[rr][0] = bcast2(a4.x); in2[rr][1] = bcast2(a4.y);
                    in2[rr][2] = bcast2(a4.z); in2[rr][3] = bcast2(a4.w);
                    in2[rr][4] = bcast2(b4.x); in2[rr][5] = bcast2(b4.y);
                    in2[rr][6] = bcast2(b4.z); in2[rr][7] = bcast2(b4.w);
                }
#pragma unroll
                for (int kw = 0; kw < 5; kw++) {
                    float2 w2 = wp[cin * 25 + kh * 5 + kw];
                    ull wt = pack2(w2.x, w2.y);
#pragma unroll
                    for (int r = 0; r < 2; r++) {
#pragma unroll
                        for (int c = 0; c < 4; c++)
                            acc[r][c] = fma2(in2[r][kw + c], wt, acc[r][c]);
                    }
                }
            }
        }

#pragma unroll
        for (int r = 0; r < 2; r++) {
            float2 u0 = unpack2(acc[r][0]);
            float2 u1 = unpack2(acc[r][1]);
            float2 u2 = unpack2(acc[r][2]);
            float2 u3 = unpack2(acc[r][3]);
            int v = r0 + lr + r;
            size_t base0 = (((size_t)b * G_ + (2 * gg)) * V_ + v) * OUTC_ + coloff + w0;
            size_t base1 = (((size_t)b * G_ + (2 * gg + 1)) * V_ + v) * OUTC_ + coloff + w0;
            *(float4*)(out + base0) = make_float4(u0.x, u1.x, u2.x, u3.x);
            *(float4*)(out + base1) = make_float4(u0.y, u1.y, u2.y, u3.y);
        }
    }
}

// ---------------- launch: 2-chunk batch pipeline, 3 worker streams ----------
extern "C" void kernel_launch(void* const* d_in, const int* in_sizes, int n_in,
                              void* d_out, int out_size) {
    const float* h       = (const float*)d_in[0];
    const int*   adj     = (const int*)d_in[1];
    const float* W       = (const float*)d_in[2];
    const float* conv1_w = (const float*)d_in[3];
    const float* conv1_b = (const float*)d_in[4];
    const float* conv2_w = (const float*)d_in[5];
    const float* conv2_b = (const float*)d_in[6];
    float* out = (float*)d_out;

    static cudaStream_t s1 = nullptr, s2 = nullptr, s3 = nullptr;
    static cudaEvent_t ev0, evW, evS, evA0, evA1, evJ1, evJ2, evJ3;
    if (s1 == nullptr) {
        cudaStreamCreateWithFlags(&s1, cudaStreamNonBlocking);
        cudaStreamCreateWithFlags(&s2, cudaStreamNonBlocking);
        cudaStreamCreateWithFlags(&s3, cudaStreamNonBlocking);
        cudaEventCreateWithFlags(&ev0, cudaEventDisableTiming);
        cudaEventCreateWithFlags(&evW, cudaEventDisableTiming);
        cudaEventCreateWithFlags(&evS, cudaEventDisableTiming);
        cudaEventCreateWithFlags(&evA0, cudaEventDisableTiming);
        cudaEventCreateWithFlags(&evA1, cudaEventDisableTiming);
        cudaEventCreateWithFlags(&evJ1, cudaEventDisableTiming);
        cudaEventCreateWithFlags(&evJ2, cudaEventDisableTiming);
        cudaEventCreateWithFlags(&evJ3, cudaEventDisableTiming);
    }

    // fork workers
    cudaEventRecord(ev0, 0);
    cudaStreamWaitEvent(s1, ev0, 0);
    cudaStreamWaitEvent(s2, ev0, 0);
    cudaStreamWaitEvent(s3, ev0, 0);

    // s1: wh + sreduce (fma-bound, overlaps adj)
    k_wh<<<dim3(16, G_, B_), 256, 0, s1>>>(h, W);
    cudaEventRecord(evW, s1);
    k_sreduce<<<64, 64, 0, s1>>>();
    cudaEventRecord(evS, s1);

    // legacy: adj in two 4-batch halves
    k_adj<<<dim3(V_, 4), 256>>>(adj, 0);
    cudaEventRecord(evA0, 0);
    k_adj<<<dim3(V_, 4), 256>>>(adj, 4);
    cudaEventRecord(evA1, 0);

    // s2: conv1 (featin fused) per half -> re-zero zcol
    cudaStreamWaitEvent(s2, evW, 0);
    cudaStreamWaitEvent(s2, evA0, 0);
    k_conv<<<dim3(V_ / 16, 4), 512, 0, s2>>>(conv1_w, conv1_b, out, 0, 0);
    cudaStreamWaitEvent(s2, evA1, 0);
    k_conv<<<dim3(V_ / 16, 4), 512, 0, s2>>>(conv1_w, conv1_b, out, 0, 4);
    k_zero<<<8, 1024, 0, s2>>>();

    // s3: featout + conv2 per half
    cudaStreamWaitEvent(s3, evS, 0);
    cudaStreamWaitEvent(s3, evA0, 0);
    k_featout<<<dim3(V_, 4), 128, 0, s3>>>(0);
    k_conv<<<dim3(V_ / 16, 4), 512, 0, s3>>>(conv2_w, conv2_b, out, 1, 0);
    cudaStreamWaitEvent(s3, evA1, 0);
    k_featout<<<dim3(V_, 4), 128, 0, s3>>>(4);
    k_conv<<<dim3(V_ / 16, 4), 512, 0, s3>>>(conv2_w, conv2_b, out, 1, 4);

    // join
    cudaEventRecord(evJ1, s1);
    cudaEventRecord(evJ2, s2);
    cudaEventRecord(evJ3, s3);
    cudaStreamWaitEvent(0, evJ1, 0);
    cudaStreamWaitEvent(0, evJ2, 0);
    cudaStreamWaitEvent(0, evJ3, 0);
}